// round 10
// baseline (speedup 1.0000x reference)
#include <cuda_runtime.h>

typedef unsigned long long u64;

// ---------- packed f32x2 helpers (sm_103a) ----------
static __device__ __forceinline__ u64 pack2(float x, float y) {
    u64 r; asm("mov.b64 %0, {%1, %2};" : "=l"(r) : "f"(x), "f"(y)); return r;
}
static __device__ __forceinline__ float2 unpack2(u64 v) {
    float2 r; asm("mov.b64 {%0, %1}, %2;" : "=f"(r.x), "=f"(r.y) : "l"(v)); return r;
}
static __device__ __forceinline__ void ffma2(u64& d, u64 a, u64 b) {
    asm("fma.rn.f32x2 %0, %1, %2, %0;" : "+l"(d) : "l"(a), "l"(b));
}
static __device__ __forceinline__ u64 fadd2(u64 a, u64 b) {
    u64 d; asm("add.rn.f32x2 %0, %1, %2;" : "=l"(d) : "l"(a), "l"(b)); return d;
}

// ---------- problem constants ----------
// B=8, H=W=256, C=192, WS=8, SHIFT=4, 6 heads x 32 dim
// tokens laid out (b, window, pixel): 8 * 1024 * 64 = 524288
#define NTOK 524288

// scratch (static __device__ arrays: allocation-guard-safe)
__device__ float g_qkv[(size_t)NTOK * 576];   // [token][576] : q|k|v per head
__device__ float g_att[(size_t)NTOK * 192];   // attention output per token

// Map token id -> source/destination pixel row in the (B,256,256) image.
// roll(-4) on input and roll(+4) on output give the identical index.
static __device__ __forceinline__ int src_row(int t) {
    int b   = t >> 16;
    int win = (t >> 6) & 1023;
    int p   = t & 63;
    int h = (((win >> 5) << 3) + (p >> 3) + 4) & 255;
    int w = (((win & 31) << 3) + (p & 7)  + 4) & 255;
    return (b << 16) | (h << 8) | w;
}

// =====================================================================
// Kernel 1: fused roll + window partition + QKV GEMM
// M = 524288 tokens, K = 192, N = 576.  CTA tile 128x64, 128 threads,
// 8x8 per thread via packed f32x2 FMA.
// =====================================================================
__global__ void __launch_bounds__(128) k_qkv(const float* __restrict__ x,
                                             const float* __restrict__ wq,
                                             const float* __restrict__ bq)
{
    __shared__ float As[16][128];
    __shared__ float Bs[16][64];
    const int tid = threadIdx.x;
    const int nb  = blockIdx.x << 6;   // 0..512
    const int t0  = blockIdx.y << 7;   // token tile base
    const int tm  = tid >> 3, tn = tid & 7;

    const float* arow = x + (size_t)src_row(t0 + tid) * 192;
    const int k0 = tid >> 4;           // 0..7
    const int j0 = (tid & 15) << 2;    // 0..60
    const int k1 = k0 + 8;

    u64 acc[8][4];
    #pragma unroll
    for (int i = 0; i < 8; ++i)
        #pragma unroll
        for (int j = 0; j < 4; ++j) acc[i][j] = 0ull;

    for (int kt = 0; kt < 192; kt += 16) {
        float4 a0 = *(const float4*)(arow + kt + 0);
        float4 a1 = *(const float4*)(arow + kt + 4);
        float4 a2 = *(const float4*)(arow + kt + 8);
        float4 a3 = *(const float4*)(arow + kt + 12);
        float4 b0 = *(const float4*)(wq + (size_t)(kt + k0) * 576 + nb + j0);
        float4 b1 = *(const float4*)(wq + (size_t)(kt + k1) * 576 + nb + j0);
        __syncthreads();
        As[0][tid] = a0.x;  As[1][tid] = a0.y;  As[2][tid] = a0.z;  As[3][tid] = a0.w;
        As[4][tid] = a1.x;  As[5][tid] = a1.y;  As[6][tid] = a1.z;  As[7][tid] = a1.w;
        As[8][tid] = a2.x;  As[9][tid] = a2.y;  As[10][tid] = a2.z; As[11][tid] = a2.w;
        As[12][tid] = a3.x; As[13][tid] = a3.y; As[14][tid] = a3.z; As[15][tid] = a3.w;
        *(float4*)&Bs[k0][j0] = b0;
        *(float4*)&Bs[k1][j0] = b1;
        __syncthreads();
        #pragma unroll
        for (int k = 0; k < 16; ++k) {
            float4 x0 = *(const float4*)&As[k][tm << 3];
            float4 x1 = *(const float4*)&As[k][(tm << 3) + 4];
            ulonglong2 u0 = *(const ulonglong2*)&Bs[k][tn << 3];
            ulonglong2 u1 = *(const ulonglong2*)&Bs[k][(tn << 3) + 4];
            u64 bb0 = u0.x, bb1 = u0.y, bb2 = u1.x, bb3 = u1.y;
            u64 aa[8];
            aa[0] = pack2(x0.x, x0.x); aa[1] = pack2(x0.y, x0.y);
            aa[2] = pack2(x0.z, x0.z); aa[3] = pack2(x0.w, x0.w);
            aa[4] = pack2(x1.x, x1.x); aa[5] = pack2(x1.y, x1.y);
            aa[6] = pack2(x1.z, x1.z); aa[7] = pack2(x1.w, x1.w);
            #pragma unroll
            for (int i = 0; i < 8; ++i) {
                ffma2(acc[i][0], aa[i], bb0);
                ffma2(acc[i][1], aa[i], bb1);
                ffma2(acc[i][2], aa[i], bb2);
                ffma2(acc[i][3], aa[i], bb3);
            }
        }
    }

    u64 bias2[4];
    #pragma unroll
    for (int j = 0; j < 4; ++j)
        bias2[j] = pack2(bq[nb + (tn << 3) + 2 * j], bq[nb + (tn << 3) + 2 * j + 1]);
    #pragma unroll
    for (int i = 0; i < 8; ++i) {
        int t = t0 + (tm << 3) + i;
        u64* dst = (u64*)(g_qkv + (size_t)t * 576 + nb + (tn << 3));
        #pragma unroll
        for (int j = 0; j < 4; ++j) dst[j] = fadd2(acc[i][j], bias2[j]);
    }
}

// =====================================================================
// Kernel 2: windowed attention. One CTA per (window, head), 64 threads.
// Thread p owns query pixel p: QK^T row, bias+mask, softmax, PV row.
// =====================================================================
__global__ void __launch_bounds__(64) k_attn(const float* __restrict__ rel_pos)
{
    __shared__ u64 ks[64][16];
    __shared__ u64 vs[64][16];
    __shared__ float bs[225];

    const int p    = threadIdx.x;
    const int wid  = blockIdx.x;          // b*1024 + window
    const int head = blockIdx.y;
    const int wh = (wid >> 5) & 31, wwc = wid & 31;
    const size_t tb = (size_t)wid << 6;
    const float* base = g_qkv + tb * 576;

    // cooperative K/V tile load (64 rows x 32 floats each)
    #pragma unroll
    for (int l = 0; l < 8; ++l) {
        int flat = (l << 6) + p;
        int row = flat >> 3, c4 = flat & 7;
        const float* kr = base + row * 576 + 192 + head * 32;
        const float* vr = base + row * 576 + 384 + head * 32;
        ((ulonglong2*)&ks[row][0])[c4] = ((const ulonglong2*)kr)[c4];
        ((ulonglong2*)&vs[row][0])[c4] = ((const ulonglong2*)vr)[c4];
    }
    for (int i = p; i < 225; i += 64) bs[i] = rel_pos[head * 225 + i];

    u64 q2[16];
    {
        const ulonglong2* qp = (const ulonglong2*)(base + p * 576 + head * 32);
        #pragma unroll
        for (int c = 0; c < 8; ++c) { ulonglong2 t = qp[c]; q2[2*c] = t.x; q2[2*c+1] = t.y; }
    }
    __syncthreads();

    const int pi = p >> 3, pj = p & 7;
    const bool lastH = (wh == 31), lastW = (wwc == 31);

    float s[64];
    #pragma unroll
    for (int q = 0; q < 64; ++q) {
        u64 a = 0ull;
        #pragma unroll
        for (int c = 0; c < 16; ++c) ffma2(a, q2[c], ks[q][c]);
        float2 f = unpack2(a);
        int qi = q >> 3, qj = q & 7;
        float v = (f.x + f.y) * 0.17677669529663687f
                + bs[(pi - qi + 7) * 15 + (pj - qj + 7)];
        bool m = (lastH && ((pi < 4) != (qi < 4))) ||
                 (lastW && ((pj < 4) != (qj < 4)));
        s[q] = m ? -1e30f : v;
    }

    float mx = -1e30f;
    #pragma unroll
    for (int q = 0; q < 64; ++q) mx = fmaxf(mx, s[q]);
    float sum = 0.f;
    #pragma unroll
    for (int q = 0; q < 64; ++q) { float e = __expf(s[q] - mx); s[q] = e; sum += e; }
    const float inv = 1.f / sum;

    u64 o[16];
    #pragma unroll
    for (int d = 0; d < 16; ++d) o[d] = 0ull;
    #pragma unroll
    for (int q = 0; q < 64; ++q) {
        float pr = s[q] * inv;
        u64 pd = pack2(pr, pr);
        #pragma unroll
        for (int d = 0; d < 16; ++d) ffma2(o[d], pd, vs[q][d]);
    }
    u64* op = (u64*)(g_att + (tb + p) * 192 + head * 32);
    #pragma unroll
    for (int d = 0; d < 16; ++d) op[d] = o[d];
}

// =====================================================================
// Kernel 3: output projection GEMM (524288 x 192 x 192) fused with the
// reverse-roll scatter into d_out.
// =====================================================================
__global__ void __launch_bounds__(128) k_out(const float* __restrict__ wo,
                                             const float* __restrict__ bo,
                                             float* __restrict__ out)
{
    __shared__ float As[16][128];
    __shared__ float Bs[16][64];
    const int tid = threadIdx.x;
    const int nb  = blockIdx.x << 6;   // 0..128
    const int t0  = blockIdx.y << 7;
    const int tm  = tid >> 3, tn = tid & 7;

    const float* arow = g_att + (size_t)(t0 + tid) * 192;
    const int k0 = tid >> 4;
    const int j0 = (tid & 15) << 2;
    const int k1 = k0 + 8;

    u64 acc[8][4];
    #pragma unroll
    for (int i = 0; i < 8; ++i)
        #pragma unroll
        for (int j = 0; j < 4; ++j) acc[i][j] = 0ull;

    for (int kt = 0; kt < 192; kt += 16) {
        float4 a0 = *(const float4*)(arow + kt + 0);
        float4 a1 = *(const float4*)(arow + kt + 4);
        float4 a2 = *(const float4*)(arow + kt + 8);
        float4 a3 = *(const float4*)(arow + kt + 12);
        float4 b0 = *(const float4*)(wo + (size_t)(kt + k0) * 192 + nb + j0);
        float4 b1 = *(const float4*)(wo + (size_t)(kt + k1) * 192 + nb + j0);
        __syncthreads();
        As[0][tid] = a0.x;  As[1][tid] = a0.y;  As[2][tid] = a0.z;  As[3][tid] = a0.w;
        As[4][tid] = a1.x;  As[5][tid] = a1.y;  As[6][tid] = a1.z;  As[7][tid] = a1.w;
        As[8][tid] = a2.x;  As[9][tid] = a2.y;  As[10][tid] = a2.z; As[11][tid] = a2.w;
        As[12][tid] = a3.x; As[13][tid] = a3.y; As[14][tid] = a3.z; As[15][tid] = a3.w;
        *(float4*)&Bs[k0][j0] = b0;
        *(float4*)&Bs[k1][j0] = b1;
        __syncthreads();
        #pragma unroll
        for (int k = 0; k < 16; ++k) {
            float4 x0 = *(const float4*)&As[k][tm << 3];
            float4 x1 = *(const float4*)&As[k][(tm << 3) + 4];
            ulonglong2 u0 = *(const ulonglong2*)&Bs[k][tn << 3];
            ulonglong2 u1 = *(const ulonglong2*)&Bs[k][(tn << 3) + 4];
            u64 bb0 = u0.x, bb1 = u0.y, bb2 = u1.x, bb3 = u1.y;
            u64 aa[8];
            aa[0] = pack2(x0.x, x0.x); aa[1] = pack2(x0.y, x0.y);
            aa[2] = pack2(x0.z, x0.z); aa[3] = pack2(x0.w, x0.w);
            aa[4] = pack2(x1.x, x1.x); aa[5] = pack2(x1.y, x1.y);
            aa[6] = pack2(x1.z, x1.z); aa[7] = pack2(x1.w, x1.w);
            #pragma unroll
            for (int i = 0; i < 8; ++i) {
                ffma2(acc[i][0], aa[i], bb0);
                ffma2(acc[i][1], aa[i], bb1);
                ffma2(acc[i][2], aa[i], bb2);
                ffma2(acc[i][3], aa[i], bb3);
            }
        }
    }

    u64 bias2[4];
    #pragma unroll
    for (int j = 0; j < 4; ++j)
        bias2[j] = pack2(bo[nb + (tn << 3) + 2 * j], bo[nb + (tn << 3) + 2 * j + 1]);
    #pragma unroll
    for (int i = 0; i < 8; ++i) {
        int t = t0 + (tm << 3) + i;
        u64* dst = (u64*)(out + (size_t)src_row(t) * 192 + nb + (tn << 3));
        #pragma unroll
        for (int j = 0; j < 4; ++j) dst[j] = fadd2(acc[i][j], bias2[j]);
    }
}

// =====================================================================
extern "C" void kernel_launch(void* const* d_in, const int* in_sizes, int n_in,
                              void* d_out, int out_size)
{
    const float* x  = (const float*)d_in[0];   // (8,256,256,192) f32
    const float* wq = (const float*)d_in[1];   // (192,576)
    const float* bq = (const float*)d_in[2];   // (576,)
    const float* rp = (const float*)d_in[3];   // (6,15,15)
    const float* wo = (const float*)d_in[4];   // (192,192)
    const float* bo = (const float*)d_in[5];   // (192,)
    float* out = (float*)d_out;                // (8,256,256,192) f32

    k_qkv <<<dim3(9, 4096), 128>>>(x, wq, bq);
    k_attn<<<dim3(8192, 6), 64>>>(rp);
    k_out <<<dim3(3, 4096), 128>>>(wo, bo, out);
}

// round 11
// speedup vs baseline: 1.0013x; 1.0013x over previous
#include <cuda_runtime.h>

typedef unsigned long long u64;

// ---------- packed f32x2 helpers (sm_103a) ----------
static __device__ __forceinline__ u64 pack2(float x, float y) {
    u64 r; asm("mov.b64 %0, {%1, %2};" : "=l"(r) : "f"(x), "f"(y)); return r;
}
static __device__ __forceinline__ float2 unpack2(u64 v) {
    float2 r; asm("mov.b64 {%0, %1}, %2;" : "=f"(r.x), "=f"(r.y) : "l"(v)); return r;
}
static __device__ __forceinline__ void ffma2(u64& d, u64 a, u64 b) {
    asm("fma.rn.f32x2 %0, %1, %2, %0;" : "+l"(d) : "l"(a), "l"(b));
}
static __device__ __forceinline__ u64 fadd2(u64 a, u64 b) {
    u64 d; asm("add.rn.f32x2 %0, %1, %2;" : "=l"(d) : "l"(a), "l"(b)); return d;
}

// ---------- problem constants ----------
// B=8, H=W=256, C=192, WS=8, SHIFT=4, 6 heads x 32 dim
// tokens laid out (b, window, pixel): 8 * 1024 * 64 = 524288
#define NTOK 524288

// scratch (static __device__ arrays: allocation-guard-safe)
__device__ float g_qkv[(size_t)NTOK * 576];   // [token][576] : q|k|v per head
__device__ float g_att[(size_t)NTOK * 192];   // attention output per token

// Map token id -> source/destination pixel row in the (B,256,256) image.
// roll(-4) on input and roll(+4) on output give the identical index.
static __device__ __forceinline__ int src_row(int t) {
    int b   = t >> 16;
    int win = (t >> 6) & 1023;
    int p   = t & 63;
    int h = (((win >> 5) << 3) + (p >> 3) + 4) & 255;
    int w = (((win & 31) << 3) + (p & 7)  + 4) & 255;
    return (b << 16) | (h << 8) | w;
}

// =====================================================================
// Kernel 1: fused roll + window partition + QKV GEMM
// M = 524288 tokens, K = 192, N = 576.  CTA tile 128x64, 128 threads,
// 8x8 per thread via packed f32x2 FMA.
// =====================================================================
__global__ void __launch_bounds__(128) k_qkv(const float* __restrict__ x,
                                             const float* __restrict__ wq,
                                             const float* __restrict__ bq)
{
    __shared__ float As[16][128];
    __shared__ float Bs[16][64];
    const int tid = threadIdx.x;
    const int nb  = blockIdx.x << 6;   // 0..512
    const int t0  = blockIdx.y << 7;   // token tile base
    const int tm  = tid >> 3, tn = tid & 7;

    const float* arow = x + (size_t)src_row(t0 + tid) * 192;
    const int k0 = tid >> 4;           // 0..7
    const int j0 = (tid & 15) << 2;    // 0..60
    const int k1 = k0 + 8;

    u64 acc[8][4];
    #pragma unroll
    for (int i = 0; i < 8; ++i)
        #pragma unroll
        for (int j = 0; j < 4; ++j) acc[i][j] = 0ull;

    for (int kt = 0; kt < 192; kt += 16) {
        float4 a0 = *(const float4*)(arow + kt + 0);
        float4 a1 = *(const float4*)(arow + kt + 4);
        float4 a2 = *(const float4*)(arow + kt + 8);
        float4 a3 = *(const float4*)(arow + kt + 12);
        float4 b0 = *(const float4*)(wq + (size_t)(kt + k0) * 576 + nb + j0);
        float4 b1 = *(const float4*)(wq + (size_t)(kt + k1) * 576 + nb + j0);
        __syncthreads();
        As[0][tid] = a0.x;  As[1][tid] = a0.y;  As[2][tid] = a0.z;  As[3][tid] = a0.w;
        As[4][tid] = a1.x;  As[5][tid] = a1.y;  As[6][tid] = a1.z;  As[7][tid] = a1.w;
        As[8][tid] = a2.x;  As[9][tid] = a2.y;  As[10][tid] = a2.z; As[11][tid] = a2.w;
        As[12][tid] = a3.x; As[13][tid] = a3.y; As[14][tid] = a3.z; As[15][tid] = a3.w;
        *(float4*)&Bs[k0][j0] = b0;
        *(float4*)&Bs[k1][j0] = b1;
        __syncthreads();
        #pragma unroll
        for (int k = 0; k < 16; ++k) {
            float4 x0 = *(const float4*)&As[k][tm << 3];
            float4 x1 = *(const float4*)&As[k][(tm << 3) + 4];
            ulonglong2 u0 = *(const ulonglong2*)&Bs[k][tn << 3];
            ulonglong2 u1 = *(const ulonglong2*)&Bs[k][(tn << 3) + 4];
            u64 bb0 = u0.x, bb1 = u0.y, bb2 = u1.x, bb3 = u1.y;
            u64 aa[8];
            aa[0] = pack2(x0.x, x0.x); aa[1] = pack2(x0.y, x0.y);
            aa[2] = pack2(x0.z, x0.z); aa[3] = pack2(x0.w, x0.w);
            aa[4] = pack2(x1.x, x1.x); aa[5] = pack2(x1.y, x1.y);
            aa[6] = pack2(x1.z, x1.z); aa[7] = pack2(x1.w, x1.w);
            #pragma unroll
            for (int i = 0; i < 8; ++i) {
                ffma2(acc[i][0], aa[i], bb0);
                ffma2(acc[i][1], aa[i], bb1);
                ffma2(acc[i][2], aa[i], bb2);
                ffma2(acc[i][3], aa[i], bb3);
            }
        }
    }

    u64 bias2[4];
    #pragma unroll
    for (int j = 0; j < 4; ++j)
        bias2[j] = pack2(bq[nb + (tn << 3) + 2 * j], bq[nb + (tn << 3) + 2 * j + 1]);
    #pragma unroll
    for (int i = 0; i < 8; ++i) {
        int t = t0 + (tm << 3) + i;
        u64* dst = (u64*)(g_qkv + (size_t)t * 576 + nb + (tn << 3));
        #pragma unroll
        for (int j = 0; j < 4; ++j) dst[j] = fadd2(acc[i][j], bias2[j]);
    }
}

// =====================================================================
// Kernel 2: windowed attention. One CTA per (window, head), 64 threads.
// Thread p owns query pixel p: QK^T row, bias+mask, softmax, PV row.
// =====================================================================
__global__ void __launch_bounds__(64) k_attn(const float* __restrict__ rel_pos)
{
    __shared__ u64 ks[64][16];
    __shared__ u64 vs[64][16];
    __shared__ float bs[225];

    const int p    = threadIdx.x;
    const int wid  = blockIdx.x;          // b*1024 + window
    const int head = blockIdx.y;
    const int wh = (wid >> 5) & 31, wwc = wid & 31;
    const size_t tb = (size_t)wid << 6;
    const float* base = g_qkv + tb * 576;

    // cooperative K/V tile load (64 rows x 32 floats each)
    #pragma unroll
    for (int l = 0; l < 8; ++l) {
        int flat = (l << 6) + p;
        int row = flat >> 3, c4 = flat & 7;
        const float* kr = base + row * 576 + 192 + head * 32;
        const float* vr = base + row * 576 + 384 + head * 32;
        ((ulonglong2*)&ks[row][0])[c4] = ((const ulonglong2*)kr)[c4];
        ((ulonglong2*)&vs[row][0])[c4] = ((const ulonglong2*)vr)[c4];
    }
    for (int i = p; i < 225; i += 64) bs[i] = rel_pos[head * 225 + i];

    u64 q2[16];
    {
        const ulonglong2* qp = (const ulonglong2*)(base + p * 576 + head * 32);
        #pragma unroll
        for (int c = 0; c < 8; ++c) { ulonglong2 t = qp[c]; q2[2*c] = t.x; q2[2*c+1] = t.y; }
    }
    __syncthreads();

    const int pi = p >> 3, pj = p & 7;
    const bool lastH = (wh == 31), lastW = (wwc == 31);

    float s[64];
    #pragma unroll
    for (int q = 0; q < 64; ++q) {
        u64 a = 0ull;
        #pragma unroll
        for (int c = 0; c < 16; ++c) ffma2(a, q2[c], ks[q][c]);
        float2 f = unpack2(a);
        int qi = q >> 3, qj = q & 7;
        float v = (f.x + f.y) * 0.17677669529663687f
                + bs[(pi - qi + 7) * 15 + (pj - qj + 7)];
        bool m = (lastH && ((pi < 4) != (qi < 4))) ||
                 (lastW && ((pj < 4) != (qj < 4)));
        s[q] = m ? -1e30f : v;
    }

    float mx = -1e30f;
    #pragma unroll
    for (int q = 0; q < 64; ++q) mx = fmaxf(mx, s[q]);
    float sum = 0.f;
    #pragma unroll
    for (int q = 0; q < 64; ++q) { float e = __expf(s[q] - mx); s[q] = e; sum += e; }
    const float inv = 1.f / sum;

    u64 o[16];
    #pragma unroll
    for (int d = 0; d < 16; ++d) o[d] = 0ull;
    #pragma unroll
    for (int q = 0; q < 64; ++q) {
        float pr = s[q] * inv;
        u64 pd = pack2(pr, pr);
        #pragma unroll
        for (int d = 0; d < 16; ++d) ffma2(o[d], pd, vs[q][d]);
    }
    u64* op = (u64*)(g_att + (tb + p) * 192 + head * 32);
    #pragma unroll
    for (int d = 0; d < 16; ++d) op[d] = o[d];
}

// =====================================================================
// Kernel 3: output projection GEMM (524288 x 192 x 192) fused with the
// reverse-roll scatter into d_out.
// =====================================================================
__global__ void __launch_bounds__(128) k_out(const float* __restrict__ wo,
                                             const float* __restrict__ bo,
                                             float* __restrict__ out)
{
    __shared__ float As[16][128];
    __shared__ float Bs[16][64];
    const int tid = threadIdx.x;
    const int nb  = blockIdx.x << 6;   // 0..128
    const int t0  = blockIdx.y << 7;
    const int tm  = tid >> 3, tn = tid & 7;

    const float* arow = g_att + (size_t)(t0 + tid) * 192;
    const int k0 = tid >> 4;
    const int j0 = (tid & 15) << 2;
    const int k1 = k0 + 8;

    u64 acc[8][4];
    #pragma unroll
    for (int i = 0; i < 8; ++i)
        #pragma unroll
        for (int j = 0; j < 4; ++j) acc[i][j] = 0ull;

    for (int kt = 0; kt < 192; kt += 16) {
        float4 a0 = *(const float4*)(arow + kt + 0);
        float4 a1 = *(const float4*)(arow + kt + 4);
        float4 a2 = *(const float4*)(arow + kt + 8);
        float4 a3 = *(const float4*)(arow + kt + 12);
        float4 b0 = *(const float4*)(wo + (size_t)(kt + k0) * 192 + nb + j0);
        float4 b1 = *(const float4*)(wo + (size_t)(kt + k1) * 192 + nb + j0);
        __syncthreads();
        As[0][tid] = a0.x;  As[1][tid] = a0.y;  As[2][tid] = a0.z;  As[3][tid] = a0.w;
        As[4][tid] = a1.x;  As[5][tid] = a1.y;  As[6][tid] = a1.z;  As[7][tid] = a1.w;
        As[8][tid] = a2.x;  As[9][tid] = a2.y;  As[10][tid] = a2.z; As[11][tid] = a2.w;
        As[12][tid] = a3.x; As[13][tid] = a3.y; As[14][tid] = a3.z; As[15][tid] = a3.w;
        *(float4*)&Bs[k0][j0] = b0;
        *(float4*)&Bs[k1][j0] = b1;
        __syncthreads();
        #pragma unroll
        for (int k = 0; k < 16; ++k) {
            float4 x0 = *(const float4*)&As[k][tm << 3];
            float4 x1 = *(const float4*)&As[k][(tm << 3) + 4];
            ulonglong2 u0 = *(const ulonglong2*)&Bs[k][tn << 3];
            ulonglong2 u1 = *(const ulonglong2*)&Bs[k][(tn << 3) + 4];
            u64 bb0 = u0.x, bb1 = u0.y, bb2 = u1.x, bb3 = u1.y;
            u64 aa[8];
            aa[0] = pack2(x0.x, x0.x); aa[1] = pack2(x0.y, x0.y);
            aa[2] = pack2(x0.z, x0.z); aa[3] = pack2(x0.w, x0.w);
            aa[4] = pack2(x1.x, x1.x); aa[5] = pack2(x1.y, x1.y);
            aa[6] = pack2(x1.z, x1.z); aa[7] = pack2(x1.w, x1.w);
            #pragma unroll
            for (int i = 0; i < 8; ++i) {
                ffma2(acc[i][0], aa[i], bb0);
                ffma2(acc[i][1], aa[i], bb1);
                ffma2(acc[i][2], aa[i], bb2);
                ffma2(acc[i][3], aa[i], bb3);
            }
        }
    }

    u64 bias2[4];
    #pragma unroll
    for (int j = 0; j < 4; ++j)
        bias2[j] = pack2(bo[nb + (tn << 3) + 2 * j], bo[nb + (tn << 3) + 2 * j + 1]);
    #pragma unroll
    for (int i = 0; i < 8; ++i) {
        int t = t0 + (tm << 3) + i;
        u64* dst = (u64*)(out + (size_t)src_row(t) * 192 + nb + (tn << 3));
        #pragma unroll
        for (int j = 0; j < 4; ++j) dst[j] = fadd2(acc[i][j], bias2[j]);
    }
}

// =====================================================================
extern "C" void kernel_launch(void* const* d_in, const int* in_sizes, int n_in,
                              void* d_out, int out_size)
{
    const float* x  = (const float*)d_in[0];   // (8,256,256,192) f32
    const float* wq = (const float*)d_in[1];   // (192,576)
    const float* bq = (const float*)d_in[2];   // (576,)
    const float* rp = (const float*)d_in[3];   // (6,15,15)
    const float* wo = (const float*)d_in[4];   // (192,192)
    const float* bo = (const float*)d_in[5];   // (192,)
    float* out = (float*)d_out;                // (8,256,256,192) f32

    k_qkv <<<dim3(9, 4096), 128>>>(x, wq, bq);
    k_attn<<<dim3(8192, 6), 64>>>(rp);
    k_out <<<dim3(3, 4096), 128>>>(wo, bo, out);
}